// round 1
// baseline (speedup 1.0000x reference)
#include <cuda_runtime.h>

#define DD    32
#define PREV  64
#define HIDN  128
#define HDIM  64
#define NW    ((DD + 1) * PREV)   // 2112
#define BATCH 8192

// Batch-independent precomputed tensors (no device mallocs allowed).
__device__ float g_w1[DD * PREV];   // [d][p]
__device__ float g_b1[PREV];
__device__ float g_Mi[DD * HIDN];   // interleaved: idx = d*128 + hh*4 + g  -> M[32g+hh][d]
__device__ float g_w2i[DD * HIDN];  // interleaved: idx = d*128 + hh*4 + g  -> w2[d][32g+hh]
__device__ float g_beffi[HIDN];     // idx = hh*4 + g
__device__ float g_ci[HIDN];        // idx = hh*4 + g

// ---------------------------------------------------------------------------
// prep1: hcode = tanh(t*hw1 + hb1);  weights = hcode @ hw2^T + hb2 -> w1, b1
// ---------------------------------------------------------------------------
__global__ void prep1_kernel(const float* __restrict__ t,
                             const float* __restrict__ hw1,
                             const float* __restrict__ hb1,
                             const float* __restrict__ hw2,
                             const float* __restrict__ hb2) {
    __shared__ float hcode[HDIM];
    int tid = threadIdx.x;
    if (tid < HDIM) {
        hcode[tid] = tanhf(t[0] * hw1[tid] + hb1[tid]);
    }
    __syncthreads();
    for (int i = tid; i < NW; i += blockDim.x) {
        float acc = hb2[i];
        const float* row = hw2 + i * HDIM;
#pragma unroll 8
        for (int j = 0; j < HDIM; j++) acc += hcode[j] * row[j];
        if (i < DD * PREV) g_w1[i] = acc;
        else               g_b1[i - DD * PREV] = acc;
    }
}

// ---------------------------------------------------------------------------
// prep2: M = bw @ w1^T (128x32), beff = bw@b1 + bb, c[h] = sum_d M[h,d]*w2[d,h]
// Stores M and w2^T in g-interleaved layout for conflict-free LDS in main.
// grid = 32 CTAs x 128 threads; CTA b owns h in [4b, 4b+4).
// ---------------------------------------------------------------------------
__global__ void prep2_kernel(const float* __restrict__ bw,
                             const float* __restrict__ bb,
                             const float* __restrict__ w2) {
    __shared__ float w1s[DD][PREV + 1];  // padded -> conflict-free across d lanes
    __shared__ float Ms[4][DD];
    int tid = threadIdx.x;
    for (int i = tid; i < DD * PREV; i += 128)
        w1s[i / PREV][i % PREV] = g_w1[i];
    __syncthreads();

    int hl = tid >> 5;          // 0..3 : h within CTA
    int d  = tid & 31;          // 0..31
    int h  = blockIdx.x * 4 + hl;
    const float* bwrow = bw + h * PREV;

    float m = 0.f;
#pragma unroll
    for (int p = 0; p < PREV; p++) m += bwrow[p] * w1s[d][p];
    Ms[hl][d] = m;

    int g = h >> 5, hh = h & 31;
    g_Mi[d * HIDN + hh * 4 + g]  = m;
    g_w2i[d * HIDN + hh * 4 + g] = w2[d * HIDN + h];
    __syncthreads();

    if (d == 0) {
        float be = bb[h];
#pragma unroll
        for (int p = 0; p < PREV; p++) be += bwrow[p] * g_b1[p];
        g_beffi[hh * 4 + g] = be;
    } else if (d == 1) {
        float c = 0.f;
#pragma unroll
        for (int dd = 0; dd < DD; dd++) c += Ms[hl][dd] * w2[dd * HIDN + h];
        g_ci[hh * 4 + g] = c;
    }
}

// ---------------------------------------------------------------------------
// main: per row b:  s[h] = x.M[h] + beff[h]; a = tanh(s);
//       out[:32] = sum_h a*w2[:,h] + b2 ; out[32] = -sum_h (1-a^2)*c[h]
// CTA = 128 threads = 32 rows x 4 h-quarters. grid = 256 CTAs.
// ---------------------------------------------------------------------------
__global__ void __launch_bounds__(128)
ode_main_kernel(const float* __restrict__ y,
                const float* __restrict__ b2,
                float* __restrict__ out) {
    __shared__ float Mi[DD * HIDN];
    __shared__ float w2i[DD * HIDN];
    __shared__ float beffi[HIDN];
    __shared__ float ci[HIDN];
    __shared__ float xs[32][33];   // stride 33 -> conflict-free row reads

    int tid = threadIdx.x;
    for (int i = tid; i < DD * HIDN; i += 128) {
        Mi[i]  = g_Mi[i];
        w2i[i] = g_w2i[i];
    }
    if (tid < HIDN) { beffi[tid] = g_beffi[tid]; ci[tid] = g_ci[tid]; }

    int rowbase = blockIdx.x * 32;
    // load 32 rows x 33 cols of y (coalesced); col 32 unused but keeps padding
    for (int i = tid; i < 32 * 33; i += 128) {
        int r = i / 33, c = i % 33;
        xs[r][c] = y[(rowbase + r) * 33 + c];
    }
    __syncthreads();

    int g  = tid & 3;     // h-quarter
    int rl = tid >> 2;    // local row 0..31

    float x[DD];
#pragma unroll
    for (int dd = 0; dd < DD; dd++) x[dd] = xs[rl][dd];

    float dx[DD];
#pragma unroll
    for (int dd = 0; dd < DD; dd++) dx[dd] = 0.f;
    float dv = 0.f;

    for (int hh = 0; hh < 32; hh++) {
        int col = hh * 4 + g;   // 4 consecutive words across g-lanes: no conflicts
        float s0 = 0.f, s1 = 0.f, s2 = 0.f, s3 = 0.f;
#pragma unroll
        for (int dd = 0; dd < DD; dd += 4) {
            s0 += Mi[(dd    ) * HIDN + col] * x[dd    ];
            s1 += Mi[(dd + 1) * HIDN + col] * x[dd + 1];
            s2 += Mi[(dd + 2) * HIDN + col] * x[dd + 2];
            s3 += Mi[(dd + 3) * HIDN + col] * x[dd + 3];
        }
        float s = (s0 + s1) + (s2 + s3) + beffi[col];
        // tanh(s) = 1 - 2/(e^{2s}+1): overflow-safe (e^inf -> a=1)
        float ex = __expf(2.f * s);
        float a  = 1.f - __fdividef(2.f, ex + 1.f);
        dv += (1.f - a * a) * ci[col];
#pragma unroll
        for (int dd = 0; dd < DD; dd++)
            dx[dd] += a * w2i[dd * HIDN + col];
    }

    // reduce across the 4 h-quarters (lanes differ only in g bits 0..1)
#pragma unroll
    for (int mask = 1; mask <= 2; mask <<= 1) {
        dv += __shfl_xor_sync(0xffffffffu, dv, mask);
#pragma unroll
        for (int dd = 0; dd < DD; dd++)
            dx[dd] += __shfl_xor_sync(0xffffffffu, dx[dd], mask);
    }

    if (g == 0) {
        float* orow = out + (rowbase + rl) * (DD + 1);
#pragma unroll
        for (int dd = 0; dd < DD; dd++)
            orow[dd] = dx[dd] + __ldg(&b2[dd]);
        orow[DD] = -dv;
    }
}

// ---------------------------------------------------------------------------
// launch: inputs in metadata order:
//  0:y 1:t 2:hw1 3:hb1 4:hw2 5:hb2 6:bw 7:bb 8:w2 9:b2
// ---------------------------------------------------------------------------
extern "C" void kernel_launch(void* const* d_in, const int* in_sizes, int n_in,
                              void* d_out, int out_size) {
    const float* y   = (const float*)d_in[0];
    const float* t   = (const float*)d_in[1];
    const float* hw1 = (const float*)d_in[2];
    const float* hb1 = (const float*)d_in[3];
    const float* hw2 = (const float*)d_in[4];
    const float* hb2 = (const float*)d_in[5];
    const float* bw  = (const float*)d_in[6];
    const float* bb  = (const float*)d_in[7];
    const float* w2  = (const float*)d_in[8];
    const float* b2  = (const float*)d_in[9];
    float* out = (float*)d_out;

    prep1_kernel<<<1, 256>>>(t, hw1, hb1, hw2, hb2);
    prep2_kernel<<<32, 128>>>(bw, bb, w2);
    ode_main_kernel<<<BATCH / 32, 128>>>(y, b2, out);
}

// round 2
// speedup vs baseline: 3.5448x; 3.5448x over previous
#include <cuda_runtime.h>

#define DD    32
#define PREV  64
#define HIDN  128
#define HDIM  64
#define NW    ((DD + 1) * PREV)   // 2112
#define BATCH 8192

// Batch-independent precomputed tensors.
__device__ float g_w1[DD * PREV];    // [d][p]
__device__ float g_b1[PREV];
__device__ float g_M[HIDN * DD];     // [h][d]   M = bw @ w1^T
__device__ float g_w2t[HIDN * DD];   // [h][d]   w2^T
__device__ float g_beff[HIDN];
__device__ float g_c[HIDN];

// ---------------------------------------------------------------------------
// prep1: hcode = tanh(t*hw1 + hb1); weights = hcode @ hw2^T + hb2 -> w1, b1
// Warp-per-output-row: 264 CTAs x 8 warps = 2112 warps.
// ---------------------------------------------------------------------------
__global__ void __launch_bounds__(256)
prep1_kernel(const float* __restrict__ t,
             const float* __restrict__ hw1,
             const float* __restrict__ hb1,
             const float* __restrict__ hw2,
             const float* __restrict__ hb2) {
    __shared__ float hcode[HDIM];
    int tid  = threadIdx.x;
    int lane = tid & 31;
    int wrp  = tid >> 5;
    if (tid < HDIM)
        hcode[tid] = tanhf(t[0] * hw1[tid] + hb1[tid]);
    __syncthreads();

    int r = blockIdx.x * 8 + wrp;            // 0..2111
    const float* row = hw2 + r * HDIM;
    float acc = hcode[lane] * row[lane] + hcode[lane + 32] * row[lane + 32];
#pragma unroll
    for (int m = 16; m >= 1; m >>= 1)
        acc += __shfl_xor_sync(0xffffffffu, acc, m);
    if (lane == 0) {
        acc += hb2[r];
        if (r < DD * PREV) g_w1[r] = acc;
        else               g_b1[r - DD * PREV] = acc;
    }
}

// ---------------------------------------------------------------------------
// prep2: M = bw @ w1^T (128x32), beff = bw@b1 + bb, c[h] = sum_d M[h,d]*w2[d,h]
// grid = 32 CTAs x 128 threads; CTA owns h in [4b, 4b+4).
// ---------------------------------------------------------------------------
__global__ void __launch_bounds__(128)
prep2_kernel(const float* __restrict__ bw,
             const float* __restrict__ bb,
             const float* __restrict__ w2) {
    __shared__ float w1s[DD][PREV + 1];
    __shared__ float Ms[4][DD];
    int tid = threadIdx.x;
    for (int i = tid; i < DD * PREV; i += 128)
        w1s[i / PREV][i % PREV] = g_w1[i];
    __syncthreads();

    int hl = tid >> 5;          // 0..3
    int d  = tid & 31;          // 0..31
    int h  = blockIdx.x * 4 + hl;
    const float* bwrow = bw + h * PREV;

    float m = 0.f;
#pragma unroll
    for (int p = 0; p < PREV; p++) m += bwrow[p] * w1s[d][p];
    Ms[hl][d] = m;

    g_M[h * DD + d]   = m;
    g_w2t[h * DD + d] = w2[d * HIDN + h];
    __syncthreads();

    if (d == 0) {
        float be = bb[h];
#pragma unroll
        for (int p = 0; p < PREV; p++) be += bwrow[p] * g_b1[p];
        g_beff[h] = be;
    } else if (d == 1) {
        float c = 0.f;
#pragma unroll
        for (int dd = 0; dd < DD; dd++) c += Ms[hl][dd] * w2[dd * HIDN + h];
        g_c[h] = c;
    }
}

// ---------------------------------------------------------------------------
// main: per row b: s[h] = x.M[h] + beff[h]; a = tanh(s)
//       out[:32] = sum_h a*w2t[h,:] + b2 ; out[32] = -sum_h (1-a^2)*c[h]
// CTA = 128 threads = 32 rows x 4 h-quarters. M/w2t in h-major padded smem
// (stride 36 floats) -> per-thread rows read as 8x LDS.128, conflict-free.
// ---------------------------------------------------------------------------
#define MSTR 36   // row stride in floats (x4B=144B: 16B aligned, cols 0..3 on distinct banks)

__global__ void __launch_bounds__(128)
ode_main_kernel(const float* __restrict__ y,
                const float* __restrict__ b2,
                float* __restrict__ out) {
    __shared__ float Mt [HIDN * MSTR];
    __shared__ float W2t[HIDN * MSTR];
    __shared__ float beff[HIDN];
    __shared__ float cs[HIDN];
    __shared__ float xs[32][33];

    int tid = threadIdx.x;
    for (int i = tid; i < HIDN * DD; i += 128) {
        int h = i >> 5, d = i & 31;
        Mt [h * MSTR + d] = g_M[i];
        W2t[h * MSTR + d] = g_w2t[i];
    }
    if (tid < HIDN) { beff[tid] = g_beff[tid]; cs[tid] = g_c[tid]; }

    int rowbase = blockIdx.x * 32;
    for (int i = tid; i < 32 * 33; i += 128) {
        int r = i / 33, c = i % 33;
        xs[r][c] = y[(rowbase + r) * 33 + c];
    }
    __syncthreads();

    int g  = tid & 3;     // h-quarter
    int rl = tid >> 2;    // local row 0..31

    float x[DD];
#pragma unroll
    for (int dd = 0; dd < DD; dd++) x[dd] = xs[rl][dd];

    float dx[DD];
#pragma unroll
    for (int dd = 0; dd < DD; dd++) dx[dd] = 0.f;
    float dv = 0.f;

#pragma unroll 2
    for (int hh = 0; hh < 32; hh++) {
        int col = hh * 4 + g;
        const float4* mrow = reinterpret_cast<const float4*>(Mt + col * MSTR);
        float s0 = 0.f, s1 = 0.f, s2 = 0.f, s3 = 0.f;
#pragma unroll
        for (int k = 0; k < 8; k++) {
            float4 mv = mrow[k];
            s0 += mv.x * x[4 * k + 0];
            s1 += mv.y * x[4 * k + 1];
            s2 += mv.z * x[4 * k + 2];
            s3 += mv.w * x[4 * k + 3];
        }
        float s = (s0 + s1) + (s2 + s3) + beff[col];
        float ex = __expf(2.f * s);
        float a  = 1.f - __fdividef(2.f, ex + 1.f);
        dv += (1.f - a * a) * cs[col];

        const float4* wrow = reinterpret_cast<const float4*>(W2t + col * MSTR);
#pragma unroll
        for (int k = 0; k < 8; k++) {
            float4 wv = wrow[k];
            dx[4 * k + 0] += a * wv.x;
            dx[4 * k + 1] += a * wv.y;
            dx[4 * k + 2] += a * wv.z;
            dx[4 * k + 3] += a * wv.w;
        }
    }

    // reduce across the 4 h-quarters
#pragma unroll
    for (int mask = 1; mask <= 2; mask <<= 1) {
        dv += __shfl_xor_sync(0xffffffffu, dv, mask);
#pragma unroll
        for (int dd = 0; dd < DD; dd++)
            dx[dd] += __shfl_xor_sync(0xffffffffu, dx[dd], mask);
    }

    if (g == 0) {
        float* orow = out + (rowbase + rl) * (DD + 1);
#pragma unroll
        for (int dd = 0; dd < DD; dd++)
            orow[dd] = dx[dd] + __ldg(&b2[dd]);
        orow[DD] = -dv;
    }
}

// ---------------------------------------------------------------------------
// inputs: 0:y 1:t 2:hw1 3:hb1 4:hw2 5:hb2 6:bw 7:bb 8:w2 9:b2
// ---------------------------------------------------------------------------
extern "C" void kernel_launch(void* const* d_in, const int* in_sizes, int n_in,
                              void* d_out, int out_size) {
    const float* y   = (const float*)d_in[0];
    const float* t   = (const float*)d_in[1];
    const float* hw1 = (const float*)d_in[2];
    const float* hb1 = (const float*)d_in[3];
    const float* hw2 = (const float*)d_in[4];
    const float* hb2 = (const float*)d_in[5];
    const float* bw  = (const float*)d_in[6];
    const float* bb  = (const float*)d_in[7];
    const float* w2  = (const float*)d_in[8];
    const float* b2  = (const float*)d_in[9];
    float* out = (float*)d_out;

    prep1_kernel<<<NW / 8, 256>>>(t, hw1, hb1, hw2, hb2);
    prep2_kernel<<<32, 128>>>(bw, bb, w2);
    ode_main_kernel<<<BATCH / 32, 128>>>(y, b2, out);
}